// round 5
// baseline (speedup 1.0000x reference)
#include <cuda_runtime.h>
#include <math.h>

// Problem: x [B=1024, T=8, V=4, D=8] fp32 -> 1 fp32 scalar.
// N=1024 samples, HIST_K=4 -> M=1020 rows, KNN_K=3, 28 (v,t) pairs.

#define FINF __int_as_float(0x7f800000)

// -------- scratch (static device arrays; no cudaMalloc anywhere) --------
__device__ float  g_E[33554432];        // 32 x 1024 x 1024 skewed Chebyshev matrices (134 MB)
__device__ float  g_MAC[4 * 1020 * 1024]; // per v: dAC rows, +inf at invalid entries
__device__ float  g_MC [4 * 1020 * 1024]; // per v: dC  rows, +inf at invalid entries
__device__ double g_psi[1024];          // psi(n+1), n = 0..1023
__device__ double g_row[28560];         // per-(pair,row) digamma contribution

// ---------------------------------------------------------------------------
// init: digamma table psi(n+1), double asymptotic series (~1e-14 accurate)
// ---------------------------------------------------------------------------
__global__ void k_init() {
    int n = threadIdx.x;                  // 0..1023
    double x = (double)n + 1.0;
    double r = 0.0;
    while (x < 10.0) { r -= 1.0 / x; x += 1.0; }
    double f = 1.0 / (x * x);
    double s = log(x) - 0.5 / x
             - f * (1.0/12.0 - f * (1.0/120.0 - f * (1.0/252.0
             - f * (1.0/240.0 - f * (1.0/132.0)))));
    g_psi[n] = r + s;
}

// ---------------------------------------------------------------------------
// phase 0: skewed per-timestep Chebyshev matrices
//   E'[vt][a][c] = max_d | S[a][d] - S[(a+c)&1023][d] |,  S = x[:, t, v, :]
// Rolling 4-row register window: one new b-row load per output row.
// grid (128, 32), 256 thr; blockIdx.x = 8-row slab, blockIdx.y = vt, c0 = 4*tid.
// ---------------------------------------------------------------------------
__device__ __forceinline__ float cheb8(float4 a0, float4 a1, float4 b0, float4 b1) {
    float m;
    m =          fabsf(a0.x - b0.x);
    m = fmaxf(m, fabsf(a0.y - b0.y));
    m = fmaxf(m, fabsf(a0.z - b0.z));
    m = fmaxf(m, fabsf(a0.w - b0.w));
    m = fmaxf(m, fabsf(a1.x - b1.x));
    m = fmaxf(m, fabsf(a1.y - b1.y));
    m = fmaxf(m, fabsf(a1.z - b1.z));
    m = fmaxf(m, fabsf(a1.w - b1.w));
    return m;
}

__global__ void __launch_bounds__(256) k_buildE(const float* __restrict__ x) {
    int vt = blockIdx.y;                  // v = vt>>3, t = vt&7
    int v  = vt >> 3, t = vt & 7;
    int a0 = blockIdx.x * 8;
    int c0 = threadIdx.x * 4;
    // float4 layout of x: (b, t, v, d4) at b*64 + t*8 + v*2 (+0/+1)
    const float4* xs = ((const float4*)x) + t * 8 + v * 2;

    float4 w[4][2];                       // rolling rows (a + c0 + k) & 1023
#pragma unroll
    for (int k = 0; k < 3; k++) {
        int b = (a0 + c0 + k) & 1023;
        w[k][0] = xs[b * 64];
        w[k][1] = xs[b * 64 + 1];
    }
    float* Ebase = g_E + ((size_t)vt << 20);
#pragma unroll
    for (int aa = 0; aa < 8; aa++) {
        int a = a0 + aa;
        int b = (a + c0 + 3) & 1023;
        int slot = (aa + 3) & 3;
        w[slot][0] = xs[b * 64];
        w[slot][1] = xs[b * 64 + 1];
        float4 ar0 = xs[a * 64], ar1 = xs[a * 64 + 1];   // uniform -> broadcast
        float4 e;
        e.x = cheb8(ar0, ar1, w[(aa + 0) & 3][0], w[(aa + 0) & 3][1]);
        e.y = cheb8(ar0, ar1, w[(aa + 1) & 3][0], w[(aa + 1) & 3][1]);
        e.z = cheb8(ar0, ar1, w[(aa + 2) & 3][0], w[(aa + 2) & 3][1]);
        e.w = cheb8(ar0, ar1, w[(aa + 3) & 3][0], w[(aa + 3) & 3][1]);
        ((float4*)(Ebase + (size_t)a * 1024))[threadIdx.x] = e;
    }
}

// ---------------------------------------------------------------------------
// phase 1: per-v target matrices (skewed), validity folded in:
//   MC [v][i][c] = max_{l=0..3} E'[v,0][i+l][c]
//   MAC[v][i][c] = max(MC, E'[v,0][i+4][c])
// c==0 (self) or j=(i+c)&1023 >= 1020 -> +inf.   grid (1020, 4), 256 thr.
// ---------------------------------------------------------------------------
__global__ void __launch_bounds__(256) k_mac() {
    int i = blockIdx.x;                   // 0..1019
    int v = blockIdx.y;                   // 0..3
    const float* e0 = g_E + ((size_t)(v * 8) << 20);
    int g = threadIdx.x;
    float4 a0 = ((const float4*)(e0 + (size_t)(i + 0) * 1024))[g];
    float4 a1 = ((const float4*)(e0 + (size_t)(i + 1) * 1024))[g];
    float4 a2 = ((const float4*)(e0 + (size_t)(i + 2) * 1024))[g];
    float4 a3 = ((const float4*)(e0 + (size_t)(i + 3) * 1024))[g];
    float4 a4 = ((const float4*)(e0 + (size_t)(i + 4) * 1024))[g];

    float4 mc, mac;
    mc.x = fmaxf(fmaxf(a0.x, a1.x), fmaxf(a2.x, a3.x));  mac.x = fmaxf(mc.x, a4.x);
    mc.y = fmaxf(fmaxf(a0.y, a1.y), fmaxf(a2.y, a3.y));  mac.y = fmaxf(mc.y, a4.y);
    mc.z = fmaxf(fmaxf(a0.z, a1.z), fmaxf(a2.z, a3.z));  mac.z = fmaxf(mc.z, a4.z);
    mc.w = fmaxf(fmaxf(a0.w, a1.w), fmaxf(a2.w, a3.w));  mac.w = fmaxf(mc.w, a4.w);

    int c = g * 4;
    if (c == 0 || (((i + c    ) & 1023) >= 1020)) { mc.x = FINF; mac.x = FINF; }
    if (          (((i + c + 1) & 1023) >= 1020)) { mc.y = FINF; mac.y = FINF; }
    if (          (((i + c + 2) & 1023) >= 1020)) { mc.z = FINF; mac.z = FINF; }
    if (          (((i + c + 3) & 1023) >= 1020)) { mc.w = FINF; mac.w = FINF; }

    size_t dst = ((size_t)(v * 1020 + i)) << 10;
    ((float4*)(g_MC  + dst))[g] = mc;
    ((float4*)(g_MAC + dst))[g] = mac;
}

// ---------------------------------------------------------------------------
// phase 2: one warp per (pair p, row i).
// Pass A: dB = max of 4 E'-rows (kept in regs), dJ = max(dB, MAC),
//         warp-wide 3-smallest -> eps.
// Pass B: counts nAC (MAC<eps), nBC (max(dB,MC)<eps), nC (MC<eps).
// +inf masking in MAC/MC handles self & boundary. grid 3570, 256 thr.
// ---------------------------------------------------------------------------
__device__ __forceinline__ void ins3(float vv, float& t0, float& t1, float& t2) {
    if (vv < t2) {
        if (vv < t1) {
            t2 = t1;
            if (vv < t0) { t1 = t0; t0 = vv; } else { t1 = vv; }
        } else { t2 = vv; }
    }
}

__global__ void __launch_bounds__(256) k_te() {
    int warp = threadIdx.x >> 5, lane = threadIdx.x & 31;
    int r = blockIdx.x * 8 + warp;        // 0..28559
    int p = r / 1020;
    int i = r - p * 1020;
    int v = p / 7;
    int t = 1 + (p - v * 7);

    const float4* e0 = (const float4*)(g_E + (((size_t)(v * 8 + t)) << 20)
                                           + (size_t)i * 1024);
    const float4* e1 = e0 + 256;          // row i+1
    const float4* e2 = e0 + 512;
    const float4* e3 = e0 + 768;
    const float4* macp = (const float4*)(g_MAC + (((size_t)(v * 1020 + i)) << 10));
    const float4* mcp  = (const float4*)(g_MC  + (((size_t)(v * 1020 + i)) << 10));

    float4 dB[8];
    float t0 = FINF, t1 = FINF, t2 = FINF;
#pragma unroll
    for (int k = 0; k < 8; k++) {
        int g = lane + 32 * k;
        float4 b0 = e0[g], b1 = e1[g], b2 = e2[g], b3 = e3[g];
        float4 d;
        d.x = fmaxf(fmaxf(b0.x, b1.x), fmaxf(b2.x, b3.x));
        d.y = fmaxf(fmaxf(b0.y, b1.y), fmaxf(b2.y, b3.y));
        d.z = fmaxf(fmaxf(b0.z, b1.z), fmaxf(b2.z, b3.z));
        d.w = fmaxf(fmaxf(b0.w, b1.w), fmaxf(b2.w, b3.w));
        dB[k] = d;
        float4 m = macp[g];
        ins3(fmaxf(d.x, m.x), t0, t1, t2);
        ins3(fmaxf(d.y, m.y), t0, t1, t2);
        ins3(fmaxf(d.z, m.z), t0, t1, t2);
        ins3(fmaxf(d.w, m.w), t0, t1, t2);
    }
#pragma unroll
    for (int off = 16; off; off >>= 1) {
        float o0 = __shfl_xor_sync(0xffffffffu, t0, off);
        float o1 = __shfl_xor_sync(0xffffffffu, t1, off);
        float o2 = __shfl_xor_sync(0xffffffffu, t2, off);
        ins3(o0, t0, t1, t2); ins3(o1, t0, t1, t2); ins3(o2, t0, t1, t2);
    }
    float eps = t2;                       // 3rd-smallest joint distance (excl. self)

    int nAC = 0, nBC = 0, nC = 0;
#pragma unroll
    for (int k = 0; k < 8; k++) {
        int g = lane + 32 * k;
        float4 m = macp[g];               // L1-hot re-read
        float4 c = mcp[g];
        float4 d = dB[k];
        nAC += (m.x < eps) + (m.y < eps) + (m.z < eps) + (m.w < eps);
        nC  += (c.x < eps) + (c.y < eps) + (c.z < eps) + (c.w < eps);
        nBC += (fmaxf(d.x, c.x) < eps) + (fmaxf(d.y, c.y) < eps)
             + (fmaxf(d.z, c.z) < eps) + (fmaxf(d.w, c.w) < eps);
    }
    nAC = __reduce_add_sync(0xffffffffu, nAC);
    nBC = __reduce_add_sync(0xffffffffu, nBC);
    nC  = __reduce_add_sync(0xffffffffu, nC);

    if (lane == 0)
        g_row[r] = g_psi[nC] - g_psi[nAC] - g_psi[nBC];
}

// ---------------------------------------------------------------------------
// final: deterministic double reduction of the 28560 row contributions.
// out = BETA/(T*V*D) * mean_v(sum_t te_p)
//     = (0.1/1024) * (28*psi(3) + S/1020),   S = sum(g_row)
// ---------------------------------------------------------------------------
__global__ void __launch_bounds__(256) k_final(float* __restrict__ out) {
    __shared__ double red[256];
    double acc = 0.0;
    for (int r = threadIdx.x; r < 28560; r += 256) acc += g_row[r];
    red[threadIdx.x] = acc;
    __syncthreads();
    for (int s = 128; s; s >>= 1) {
        if (threadIdx.x < s) red[threadIdx.x] += red[threadIdx.x + s];
        __syncthreads();
    }
    if (threadIdx.x == 0) {
        const double PSI3 = 0.9227843350984671;   // digamma(3)
        double S = red[0];
        out[0] = (float)((0.1 / 1024.0) * (28.0 * PSI3 + S / 1020.0));
    }
}

extern "C" void kernel_launch(void* const* d_in, const int* in_sizes, int n_in,
                              void* d_out, int out_size) {
    const float* x = (const float*)d_in[0];
    float* out = (float*)d_out;

    k_init  <<<1, 1024>>>();
    k_buildE<<<dim3(128, 32), 256>>>(x);
    k_mac   <<<dim3(1020, 4), 256>>>();
    k_te    <<<3570, 256>>>();
    k_final <<<1, 256>>>(out);
}

// round 14
// speedup vs baseline: 1.3479x; 1.3479x over previous
#include <cuda_runtime.h>
#include <math.h>

// Problem: x [B=1024, T=8, V=4, D=8] fp32 -> 1 fp32 scalar.
// N=1024 samples, HIST_K=4 -> M=1020 rows, KNN_K=3, 28 (v,t) pairs.

#define FINF __int_as_float(0x7f800000)

// -------- scratch (static device arrays; no cudaMalloc anywhere) --------
__device__ float  g_E[33554432];        // 32 x 1024 x 1024 skewed Chebyshev matrices (134 MB)
__device__ double g_psi[1024];          // psi(n+1), n = 0..1023
__device__ double g_row[28560];         // per-(pair,row) digamma contribution

// ---------------------------------------------------------------------------
// init: digamma table psi(n+1), double asymptotic series (~1e-14 accurate)
// ---------------------------------------------------------------------------
__global__ void k_init() {
    int n = threadIdx.x;                  // 0..1023
    double x = (double)n + 1.0;
    double r = 0.0;
    while (x < 10.0) { r -= 1.0 / x; x += 1.0; }
    double f = 1.0 / (x * x);
    double s = log(x) - 0.5 / x
             - f * (1.0/12.0 - f * (1.0/120.0 - f * (1.0/252.0
             - f * (1.0/240.0 - f * (1.0/132.0)))));
    g_psi[n] = r + s;
}

// ---------------------------------------------------------------------------
// phase 0: skewed per-timestep Chebyshev matrices
//   E'[vt][a][c] = max_d | S[a][d] - S[(a+c)&1023][d] |,  S = x[:, t, v, :]
// The 1024-row slice (8 floats/row = two float4 halves) is staged in XOR-
// swizzled smem: half (b,h) lives at s4[(2b+h) ^ (((2b+h)>>3)&7)]. A warp's
// window reads (lane b-stride 4 -> float4-index stride 8) then hit all 32
// banks exactly once per LDS.128 phase. Same sw4 map on write and read, so
// layout cannot affect correctness. Rolling 4-row window, 4 cols/thread.
// grid (32, 32), 256 thr; blockIdx.x = 32-row slab, blockIdx.y = vt.
// ---------------------------------------------------------------------------
__device__ __forceinline__ int sw4(int a4) { return a4 ^ ((a4 >> 3) & 7); }

__device__ __forceinline__ float cheb8(float4 a0, float4 a1, float4 b0, float4 b1) {
    float m;
    m =          fabsf(a0.x - b0.x);
    m = fmaxf(m, fabsf(a0.y - b0.y));
    m = fmaxf(m, fabsf(a0.z - b0.z));
    m = fmaxf(m, fabsf(a0.w - b0.w));
    m = fmaxf(m, fabsf(a1.x - b1.x));
    m = fmaxf(m, fabsf(a1.y - b1.y));
    m = fmaxf(m, fabsf(a1.z - b1.z));
    m = fmaxf(m, fabsf(a1.w - b1.w));
    return m;
}

__global__ void __launch_bounds__(256) k_buildE(const float* __restrict__ x) {
    __shared__ float4 s4[2048];           // 1024 rows x 2 halves, swizzled (32KB)
    int vt = blockIdx.y;                  // v = vt>>3, t = vt&7
    int v  = vt >> 3, t = vt & 7;
    int a0 = blockIdx.x * 32;
    int c0 = threadIdx.x * 4;
    // float4 layout of x: (b, t, v, d4) at b*64 + t*8 + v*2 (+0/+1)
    const float4* xs = ((const float4*)x) + t * 8 + v * 2;

    // stage full slice: half (b,h) from gmem -> swizzled smem
#pragma unroll
    for (int e = threadIdx.x; e < 2048; e += 256) {
        int b = e >> 1, h = e & 1;
        s4[sw4(e)] = xs[b * 64 + h];      // e == 2*b + h
    }
    __syncthreads();

    float4 w[4][2];                       // rolling rows (a + c0 + k) & 1023
#pragma unroll
    for (int k = 0; k < 3; k++) {
        int bb = (a0 + c0 + k) & 1023;
        w[k][0] = s4[sw4(2 * bb    )];
        w[k][1] = s4[sw4(2 * bb + 1)];
    }
    float* Ebase = g_E + ((size_t)vt << 20);
#pragma unroll 4
    for (int aa = 0; aa < 32; aa++) {
        int a = a0 + aa;
        int bb = (a + c0 + 3) & 1023;
        int slot = (aa + 3) & 3;
        w[slot][0] = s4[sw4(2 * bb    )];
        w[slot][1] = s4[sw4(2 * bb + 1)];
        float4 ar0 = s4[sw4(2 * a)];      // uniform -> smem broadcast
        float4 ar1 = s4[sw4(2 * a + 1)];
        float4 e;
        e.x = cheb8(ar0, ar1, w[(aa + 0) & 3][0], w[(aa + 0) & 3][1]);
        e.y = cheb8(ar0, ar1, w[(aa + 1) & 3][0], w[(aa + 1) & 3][1]);
        e.z = cheb8(ar0, ar1, w[(aa + 2) & 3][0], w[(aa + 2) & 3][1]);
        e.w = cheb8(ar0, ar1, w[(aa + 3) & 3][0], w[(aa + 3) & 3][1]);
        ((float4*)(Ebase + (size_t)a * 1024))[threadIdx.x] = e;
    }
}

// ---------------------------------------------------------------------------
// fused TE: one warp owns (v, i); target-side quantities computed ONCE from
// 5 rows of E'[v,0] and held in registers across all 7 sources t=1..7:
//   mc  = max_{l=0..3} E'[v,0][i+l][c]   (masked +inf at c==0 / j>=1020)
//   mac = max(mc, E'[v,0][i+4][c])
// Per t: pass A loads 4 src rows, dB cached in regs, dJ = max(dB, mac),
// warp 3-smallest -> eps; pass B is register-only (counts from mc/mac/dB).
// grid (255, 4), 128 thr (4 warps): i = bx*4 + warp, exactly 1020 rows.
// ---------------------------------------------------------------------------
__device__ __forceinline__ void ins3(float vv, float& t0, float& t1, float& t2) {
    if (vv < t2) {
        if (vv < t1) {
            t2 = t1;
            if (vv < t0) { t1 = t0; t0 = vv; } else { t1 = vv; }
        } else { t2 = vv; }
    }
}

__global__ void __launch_bounds__(128) k_te() {
    int warp = threadIdx.x >> 5, lane = threadIdx.x & 31;
    int v = blockIdx.y;                   // 0..3
    int i = blockIdx.x * 4 + warp;        // 0..1019

    const float* et = g_E + ((size_t)(v * 8) << 20) + (size_t)i * 1024;

    float4 mc[8], mac[8];
#pragma unroll
    for (int k = 0; k < 8; k++) {
        int g = lane + 32 * k;
        float4 a0 = ((const float4*)(et       ))[g];
        float4 a1 = ((const float4*)(et + 1024))[g];
        float4 a2 = ((const float4*)(et + 2048))[g];
        float4 a3 = ((const float4*)(et + 3072))[g];
        float4 a4 = ((const float4*)(et + 4096))[g];
        float4 m;
        m.x = fmaxf(fmaxf(a0.x, a1.x), fmaxf(a2.x, a3.x));
        m.y = fmaxf(fmaxf(a0.y, a1.y), fmaxf(a2.y, a3.y));
        m.z = fmaxf(fmaxf(a0.z, a1.z), fmaxf(a2.z, a3.z));
        m.w = fmaxf(fmaxf(a0.w, a1.w), fmaxf(a2.w, a3.w));
        int c = g * 4;
        if (c == 0 || (((i + c    ) & 1023) >= 1020)) m.x = FINF;
        if (          (((i + c + 1) & 1023) >= 1020)) m.y = FINF;
        if (          (((i + c + 2) & 1023) >= 1020)) m.z = FINF;
        if (          (((i + c + 3) & 1023) >= 1020)) m.w = FINF;
        mc[k] = m;
        mac[k].x = fmaxf(m.x, a4.x);
        mac[k].y = fmaxf(m.y, a4.y);
        mac[k].z = fmaxf(m.z, a4.z);
        mac[k].w = fmaxf(m.w, a4.w);
    }

#pragma unroll 1
    for (int t = 1; t <= 7; t++) {
        const float4* es = (const float4*)(g_E + (((size_t)(v * 8 + t)) << 20)
                                               + (size_t)i * 1024);
        float4 dB[8];
        float t0 = FINF, t1 = FINF, t2 = FINF;
#pragma unroll
        for (int k = 0; k < 8; k++) {
            int g = lane + 32 * k;
            float4 b0 = es[g], b1 = es[g + 256], b2 = es[g + 512], b3 = es[g + 768];
            float4 d;
            d.x = fmaxf(fmaxf(b0.x, b1.x), fmaxf(b2.x, b3.x));
            d.y = fmaxf(fmaxf(b0.y, b1.y), fmaxf(b2.y, b3.y));
            d.z = fmaxf(fmaxf(b0.z, b1.z), fmaxf(b2.z, b3.z));
            d.w = fmaxf(fmaxf(b0.w, b1.w), fmaxf(b2.w, b3.w));
            dB[k] = d;
            ins3(fmaxf(d.x, mac[k].x), t0, t1, t2);
            ins3(fmaxf(d.y, mac[k].y), t0, t1, t2);
            ins3(fmaxf(d.z, mac[k].z), t0, t1, t2);
            ins3(fmaxf(d.w, mac[k].w), t0, t1, t2);
        }
#pragma unroll
        for (int off = 16; off; off >>= 1) {
            float o0 = __shfl_xor_sync(0xffffffffu, t0, off);
            float o1 = __shfl_xor_sync(0xffffffffu, t1, off);
            float o2 = __shfl_xor_sync(0xffffffffu, t2, off);
            ins3(o0, t0, t1, t2); ins3(o1, t0, t1, t2); ins3(o2, t0, t1, t2);
        }
        float eps = t2;                   // 3rd-smallest joint distance (excl. self)

        int nAC = 0, nBC = 0, nC = 0;
#pragma unroll
        for (int k = 0; k < 8; k++) {
            float4 m = mac[k], c4 = mc[k], d = dB[k];
            nAC += (m.x  < eps) + (m.y  < eps) + (m.z  < eps) + (m.w  < eps);
            nC  += (c4.x < eps) + (c4.y < eps) + (c4.z < eps) + (c4.w < eps);
            nBC += (fmaxf(d.x, c4.x) < eps) + (fmaxf(d.y, c4.y) < eps)
                 + (fmaxf(d.z, c4.z) < eps) + (fmaxf(d.w, c4.w) < eps);
        }
        nAC = __reduce_add_sync(0xffffffffu, nAC);
        nBC = __reduce_add_sync(0xffffffffu, nBC);
        nC  = __reduce_add_sync(0xffffffffu, nC);

        if (lane == 0)
            g_row[(v * 7 + (t - 1)) * 1020 + i] = g_psi[nC] - g_psi[nAC] - g_psi[nBC];
    }
}

// ---------------------------------------------------------------------------
// final: deterministic double reduction of the 28560 row contributions.
// out = BETA/(T*V*D) * mean_v(sum_t te_p)
//     = (0.1/1024) * (28*psi(3) + S/1020),   S = sum(g_row)
// ---------------------------------------------------------------------------
__global__ void __launch_bounds__(256) k_final(float* __restrict__ out) {
    __shared__ double red[256];
    double acc = 0.0;
    for (int r = threadIdx.x; r < 28560; r += 256) acc += g_row[r];
    red[threadIdx.x] = acc;
    __syncthreads();
    for (int s = 128; s; s >>= 1) {
        if (threadIdx.x < s) red[threadIdx.x] += red[threadIdx.x + s];
        __syncthreads();
    }
    if (threadIdx.x == 0) {
        const double PSI3 = 0.9227843350984671;   // digamma(3)
        double S = red[0];
        out[0] = (float)((0.1 / 1024.0) * (28.0 * PSI3 + S / 1020.0));
    }
}

extern "C" void kernel_launch(void* const* d_in, const int* in_sizes, int n_in,
                              void* d_out, int out_size) {
    const float* x = (const float*)d_in[0];
    float* out = (float*)d_out;

    k_init  <<<1, 1024>>>();
    k_buildE<<<dim3(32, 32), 256>>>(x);
    k_te    <<<dim3(255, 4), 128>>>();
    k_final <<<1, 256>>>(out);
}